// round 1
// baseline (speedup 1.0000x reference)
#include <cuda_runtime.h>
#include <cuda_bf16.h>
#include <math.h>

// ---------------- problem constants ----------------
#define Bb 2
#define Ll 2048
#define DM 512
#define DI 1024
#define DS 16
#define DR 32
#define DC 4
#define Mrows (Bb*Ll)          // 4096

// ---------------- scratch (device globals; allocation-free) ----------------
__device__ float g_xrev[(size_t)Mrows*DM];
__device__ float g_xz  [2][(size_t)Mrows*2*DI];
__device__ float g_xc  [2][(size_t)Mrows*DI];
__device__ float g_proj[2][(size_t)Mrows*64];
__device__ float g_dt  [2][(size_t)Mrows*DI];
__device__ float g_yg  [2][(size_t)Mrows*DI];
__device__ float g_od  [2][(size_t)Mrows*DM];

// ---------------- helpers ----------------
__device__ __forceinline__ float softplusf(float x) {
    return fmaxf(x, 0.f) + log1pf(__expf(-fabsf(x)));
}
__device__ __forceinline__ float siluf(float x) {
    return x / (1.f + __expf(-x));
}

// ---------------- param structs (2 directions) ----------------
struct GemmP {
    const float* A[2];
    const float* W[2];
    float*       C[2];
    const float* bias[2];
};
struct ConvP {
    const float* xz[2];
    float*       xc[2];
    const float* cw[2];
    const float* cb[2];
};
struct ScanP {
    const float* dt[2];
    const float* xc[2];
    const float* proj[2];
    const float* xz[2];     // z lives at offset +DI inside row of 2*DI
    const float* Alog[2];
    const float* Dsk[2];
    float*       yg[2];
};

// ---------------- flip x over L ----------------
__global__ void flip_x_kernel(const float* __restrict__ x, float* __restrict__ xr) {
    int i = blockIdx.x * blockDim.x + threadIdx.x;
    if (i >= Mrows * DM) return;
    int c  = i & (DM - 1);
    int bl = i >> 9;
    int l  = bl & (Ll - 1);
    int b  = bl >> 11;
    xr[i] = x[(((size_t)b * Ll + (Ll - 1 - l)) << 9) + c];
}

// ---------------- generic NT SGEMM: C[M,N] = A[M,K] * W[N,K]^T ----------------
// 128x128 tile, BK=16, 256 threads, 8x8 per-thread microtile. M,K multiples of 16.
template <int EPI>
__global__ __launch_bounds__(256)
void sgemm_nt(GemmP p, int M, int N, int K, int lda, int ldb, int ldc) {
    const int dir = blockIdx.z;
    const float* __restrict__ A = p.A[dir];
    const float* __restrict__ W = p.W[dir];
    float*       __restrict__ C = p.C[dir];
    const float* bias = p.bias[dir];

    const int cm = blockIdx.y * 128;
    const int cn = blockIdx.x * 128;

    __shared__ float As[16][128];
    __shared__ float Bs[16][128];

    float acc[8][8];
#pragma unroll
    for (int i = 0; i < 8; i++)
#pragma unroll
        for (int j = 0; j < 8; j++) acc[i][j] = 0.f;

    const int t  = threadIdx.x;
    const int tr = t >> 4;
    const int tc = t & 15;

    for (int k0 = 0; k0 < K; k0 += 16) {
#pragma unroll
        for (int i = 0; i < 2; i++) {
            int id  = t * 2 + i;
            int row = id >> 2;
            int kq  = (id & 3) * 4;
            float4 av = *(const float4*)(A + (size_t)(cm + row) * lda + k0 + kq);
            As[kq + 0][row] = av.x; As[kq + 1][row] = av.y;
            As[kq + 2][row] = av.z; As[kq + 3][row] = av.w;
            float4 wv = make_float4(0.f, 0.f, 0.f, 0.f);
            if (cn + row < N)
                wv = *(const float4*)(W + (size_t)(cn + row) * ldb + k0 + kq);
            Bs[kq + 0][row] = wv.x; Bs[kq + 1][row] = wv.y;
            Bs[kq + 2][row] = wv.z; Bs[kq + 3][row] = wv.w;
        }
        __syncthreads();
#pragma unroll
        for (int k = 0; k < 16; k++) {
            float a[8], bq[8];
            *(float4*)&a[0]  = *(const float4*)&As[k][tr * 8];
            *(float4*)&a[4]  = *(const float4*)&As[k][tr * 8 + 4];
            *(float4*)&bq[0] = *(const float4*)&Bs[k][tc * 8];
            *(float4*)&bq[4] = *(const float4*)&Bs[k][tc * 8 + 4];
#pragma unroll
            for (int i = 0; i < 8; i++)
#pragma unroll
                for (int j = 0; j < 8; j++)
                    acc[i][j] = fmaf(a[i], bq[j], acc[i][j]);
        }
        __syncthreads();
    }

    const bool fullN = (cn + 128 <= N);
#pragma unroll
    for (int i = 0; i < 8; i++) {
        int row = cm + tr * 8 + i;
        float* Crow = C + (size_t)row * ldc;
        if (fullN && EPI == 0) {
            float4 v0 = make_float4(acc[i][0], acc[i][1], acc[i][2], acc[i][3]);
            float4 v1 = make_float4(acc[i][4], acc[i][5], acc[i][6], acc[i][7]);
            *(float4*)(Crow + cn + tc * 8)     = v0;
            *(float4*)(Crow + cn + tc * 8 + 4) = v1;
        } else {
#pragma unroll
            for (int j = 0; j < 8; j++) {
                int col = cn + tc * 8 + j;
                if (col < N) {
                    float v = acc[i][j];
                    if (EPI == 1) v = softplusf(v + bias[col]);
                    Crow[col] = v;
                }
            }
        }
    }
}

// ---------------- causal depthwise conv(4) + bias + silu ----------------
__global__ void conv_silu_kernel(ConvP p) {
    const int dir = blockIdx.y;
    const float* __restrict__ xz = p.xz[dir];
    float*       __restrict__ xc = p.xc[dir];
    const float* __restrict__ cw = p.cw[dir];
    const float* __restrict__ cb = p.cb[dir];

    int i = blockIdx.x * blockDim.x + threadIdx.x;
    if (i >= Mrows * DI) return;
    int d  = i & (DI - 1);
    int bl = i >> 10;
    int l  = bl & (Ll - 1);
    int b  = bl >> 11;

    float w0 = cw[d * 4 + 0], w1 = cw[d * 4 + 1], w2 = cw[d * 4 + 2], w3 = cw[d * 4 + 3];
    float s = cb[d];
    size_t base = ((size_t)b * Ll) * (2 * DI) + d;
    if (l >= 3) s = fmaf(xz[base + (size_t)(l - 3) * (2 * DI)], w0, s);
    if (l >= 2) s = fmaf(xz[base + (size_t)(l - 2) * (2 * DI)], w1, s);
    if (l >= 1) s = fmaf(xz[base + (size_t)(l - 1) * (2 * DI)], w2, s);
    s = fmaf(xz[base + (size_t)l * (2 * DI)], w3, s);
    xc[i] = siluf(s);
}

// ---------------- selective scan: 16 lanes per (b,d); fused D-skip + z-gate ----------------
__global__ void scan_kernel(ScanP p) {
    const int dir = blockIdx.y;
    const float* __restrict__ dt   = p.dt[dir];
    const float* __restrict__ xc   = p.xc[dir];
    const float* __restrict__ proj = p.proj[dir];
    const float* __restrict__ xz   = p.xz[dir];
    const float* __restrict__ Alog = p.Alog[dir];
    const float* __restrict__ Dsk  = p.Dsk[dir];
    float*       __restrict__ yg   = p.yg[dir];

    int tid = blockIdx.x * blockDim.x + threadIdx.x;
    int grp = tid >> 4;
    int n   = tid & 15;
    if (grp >= Bb * DI) return;
    int b = grp >> 10;
    int d = grp & (DI - 1);

    const float Ad = -__expf(Alog[d * DS + n]);
    const float Dv = Dsk[d];
    float h = 0.f;

    size_t r = (size_t)b * Ll;
#pragma unroll 2
    for (int l = 0; l < Ll; l++, r++) {
        float dtv = dt[r * DI + d];
        float u   = xc[r * DI + d];
        float Bv  = proj[r * 64 + 32 + n];
        float Cv  = proj[r * 64 + 48 + n];
        float dA  = __expf(dtv * Ad);
        h = fmaf(dA, h, dtv * Bv * u);
        float y = h * Cv;
        y += __shfl_xor_sync(0xffffffffu, y, 8);
        y += __shfl_xor_sync(0xffffffffu, y, 4);
        y += __shfl_xor_sync(0xffffffffu, y, 2);
        y += __shfl_xor_sync(0xffffffffu, y, 1);
        if (n == 0) {
            float zv = xz[r * (2 * DI) + DI + d];
            yg[r * DI + d] = (y + u * Dv) * siluf(zv);
        }
    }
}

// ---------------- combine fw + flipped bw, LayerNorm, silu + residual ----------------
__global__ void combine_kernel(const float* __restrict__ f,
                               const float* __restrict__ bw,
                               const float* __restrict__ x,
                               const float* __restrict__ g,
                               const float* __restrict__ beta,
                               float* __restrict__ out) {
    int row = blockIdx.x;              // b*L + l
    int b = row >> 11;
    int l = row & (Ll - 1);
    const float* fr = f  + (size_t)row * DM;
    const float* br = bw + ((size_t)b * Ll + (Ll - 1 - l)) * DM;

    int c0 = threadIdx.x;
    int c1 = threadIdx.x + 256;
    float v0 = 0.5f * (fr[c0] + br[c0]);
    float v1 = 0.5f * (fr[c1] + br[c1]);

    float s1 = v0 + v1;
    float s2 = v0 * v0 + v1 * v1;
#pragma unroll
    for (int o = 16; o; o >>= 1) {
        s1 += __shfl_xor_sync(0xffffffffu, s1, o);
        s2 += __shfl_xor_sync(0xffffffffu, s2, o);
    }
    __shared__ float sh1[8], sh2[8];
    __shared__ float s_mu, s_rstd;
    int w = threadIdx.x >> 5, ln = threadIdx.x & 31;
    if (ln == 0) { sh1[w] = s1; sh2[w] = s2; }
    __syncthreads();
    if (threadIdx.x == 0) {
        float a = 0.f, q = 0.f;
#pragma unroll
        for (int i = 0; i < 8; i++) { a += sh1[i]; q += sh2[i]; }
        float mu  = a * (1.f / DM);
        float var = q * (1.f / DM) - mu * mu;
        s_mu   = mu;
        s_rstd = rsqrtf(var + 1e-5f);
    }
    __syncthreads();
    float mu = s_mu, rstd = s_rstd;
    const float* xr = x + (size_t)row * DM;
    float o0 = (v0 - mu) * rstd * g[c0] + beta[c0];
    float o1 = (v1 - mu) * rstd * g[c1] + beta[c1];
    out[(size_t)row * DM + c0] = siluf(o0) + xr[c0];
    out[(size_t)row * DM + c1] = siluf(o1) + xr[c1];
}

// ---------------- launch ----------------
extern "C" void kernel_launch(void* const* d_in, const int* in_sizes, int n_in,
                              void* d_out, int out_size) {
    const float* x = (const float*)d_in[0];
    // fw params
    const float* fW_in  = (const float*)d_in[1];
    const float* fcw    = (const float*)d_in[2];
    const float* fcb    = (const float*)d_in[3];
    const float* fWxp   = (const float*)d_in[4];
    const float* fWdt   = (const float*)d_in[5];
    const float* fbdt   = (const float*)d_in[6];
    const float* fAlog  = (const float*)d_in[7];
    const float* fDsk   = (const float*)d_in[8];
    const float* fWout  = (const float*)d_in[9];
    // bw params
    const float* bW_in  = (const float*)d_in[10];
    const float* bcw    = (const float*)d_in[11];
    const float* bcb    = (const float*)d_in[12];
    const float* bWxp   = (const float*)d_in[13];
    const float* bWdt   = (const float*)d_in[14];
    const float* bbdt   = (const float*)d_in[15];
    const float* bAlog  = (const float*)d_in[16];
    const float* bDsk   = (const float*)d_in[17];
    const float* bWout  = (const float*)d_in[18];
    const float* ln_g   = (const float*)d_in[19];
    const float* ln_b   = (const float*)d_in[20];
    float* out = (float*)d_out;

    float *xrev, *xz, *xc, *proj, *dtb, *ygb, *od;
    cudaGetSymbolAddress((void**)&xrev, g_xrev);
    cudaGetSymbolAddress((void**)&xz,   g_xz);
    cudaGetSymbolAddress((void**)&xc,   g_xc);
    cudaGetSymbolAddress((void**)&proj, g_proj);
    cudaGetSymbolAddress((void**)&dtb,  g_dt);
    cudaGetSymbolAddress((void**)&ygb,  g_yg);
    cudaGetSymbolAddress((void**)&od,   g_od);

    const size_t SXZ = (size_t)Mrows * 2 * DI;
    const size_t SXC = (size_t)Mrows * DI;
    const size_t SPJ = (size_t)Mrows * 64;
    const size_t SOD = (size_t)Mrows * DM;

    float* xz0 = xz;            float* xz1 = xz + SXZ;
    float* xc0 = xc;            float* xc1 = xc + SXC;
    float* pj0 = proj;          float* pj1 = proj + SPJ;
    float* dt0 = dtb;           float* dt1 = dtb + SXC;
    float* yg0 = ygb;           float* yg1 = ygb + SXC;
    float* od0 = od;            float* od1 = od + SOD;

    // 1. flip x
    flip_x_kernel<<<(Mrows * DM + 255) / 256, 256>>>(x, xrev);

    // 2. GEMM1: xz = A * W_in^T   [4096,512] x [2048,512]^T
    {
        GemmP p;
        p.A[0] = x;    p.A[1] = xrev;
        p.W[0] = fW_in; p.W[1] = bW_in;
        p.C[0] = xz0;  p.C[1] = xz1;
        p.bias[0] = nullptr; p.bias[1] = nullptr;
        dim3 grid(2 * DI / 128, Mrows / 128, 2);
        sgemm_nt<0><<<grid, 256>>>(p, Mrows, 2 * DI, DM, DM, DM, 2 * DI);
    }

    // 3. conv + silu
    {
        ConvP p;
        p.xz[0] = xz0; p.xz[1] = xz1;
        p.xc[0] = xc0; p.xc[1] = xc1;
        p.cw[0] = fcw; p.cw[1] = bcw;
        p.cb[0] = fcb; p.cb[1] = bcb;
        dim3 grid((Mrows * DI + 255) / 256, 2);
        conv_silu_kernel<<<grid, 256>>>(p);
    }

    // 4. GEMM2: proj = xc * Wxp^T   [4096,1024] x [64,1024]^T
    {
        GemmP p;
        p.A[0] = xc0; p.A[1] = xc1;
        p.W[0] = fWxp; p.W[1] = bWxp;
        p.C[0] = pj0; p.C[1] = pj1;
        p.bias[0] = nullptr; p.bias[1] = nullptr;
        dim3 grid(1, Mrows / 128, 2);
        sgemm_nt<0><<<grid, 256>>>(p, Mrows, 64, DI, DI, DI, 64);
    }

    // 5. GEMM3: dt = softplus(dtpart * Wdt^T + b_dt)  [4096,32(stride 64)] x [1024,32]^T
    {
        GemmP p;
        p.A[0] = pj0; p.A[1] = pj1;
        p.W[0] = fWdt; p.W[1] = bWdt;
        p.C[0] = dt0; p.C[1] = dt1;
        p.bias[0] = fbdt; p.bias[1] = bbdt;
        dim3 grid(DI / 128, Mrows / 128, 2);
        sgemm_nt<1><<<grid, 256>>>(p, Mrows, DI, DR, 64, DR, DI);
    }

    // 6. scan (+ D skip + z gate)
    {
        ScanP p;
        p.dt[0] = dt0;  p.dt[1] = dt1;
        p.xc[0] = xc0;  p.xc[1] = xc1;
        p.proj[0] = pj0; p.proj[1] = pj1;
        p.xz[0] = xz0;  p.xz[1] = xz1;
        p.Alog[0] = fAlog; p.Alog[1] = bAlog;
        p.Dsk[0] = fDsk;   p.Dsk[1] = bDsk;
        p.yg[0] = yg0;  p.yg[1] = yg1;
        dim3 grid((Bb * DI * DS + 255) / 256, 2);
        scan_kernel<<<grid, 256>>>(p);
    }

    // 7. GEMM4: od = yg * Wout^T   [4096,1024] x [512,1024]^T
    {
        GemmP p;
        p.A[0] = yg0; p.A[1] = yg1;
        p.W[0] = fWout; p.W[1] = bWout;
        p.C[0] = od0; p.C[1] = od1;
        p.bias[0] = nullptr; p.bias[1] = nullptr;
        dim3 grid(DM / 128, Mrows / 128, 2);
        sgemm_nt<0><<<grid, 256>>>(p, Mrows, DM, DI, DI, DI, DM);
    }

    // 8. combine + LN + silu + residual
    combine_kernel<<<Mrows, 256>>>(od0, od1, x, ln_g, ln_b, out);
}

// round 2
// speedup vs baseline: 1.6847x; 1.6847x over previous
#include <cuda_runtime.h>
#include <cuda_bf16.h>
#include <math.h>

// ---------------- problem constants ----------------
#define Bb 2
#define Ll 2048
#define DM 512
#define DI 1024
#define DS 16
#define DR 32
#define Mrows (Bb*Ll)          // 4096
#define NSLICE 8               // split-K slices for GEMM2

// ---------------- scratch (device globals; allocation-free) ----------------
__device__ float g_xz  [2][(size_t)Mrows*2*DI];
__device__ float g_xc  [2][(size_t)Mrows*DI];
__device__ float g_proj[2][(size_t)Mrows*64];
__device__ float g_pp  [2][NSLICE][(size_t)Mrows*64];
__device__ float g_dt  [2][(size_t)Mrows*DI];
__device__ float g_yg  [2][(size_t)Mrows*DI];
__device__ float g_od  [2][(size_t)Mrows*DM];

// ---------------- helpers ----------------
__device__ __forceinline__ float softplusf(float x) {
    return fmaxf(x, 0.f) + log1pf(__expf(-fabsf(x)));
}
__device__ __forceinline__ float siluf(float x) {
    return x / (1.f + __expf(-x));
}

// ---------------- param structs (2 directions) ----------------
struct GemmP {
    const float* A[2];
    const float* W[2];
    float*       C[2];
    const float* bias[2];
};
struct ConvP {
    const float* xz[2];
    float*       xc[2];
    const float* cw[2];
    const float* cb[2];
};
struct ScanP {
    const float* dt[2];
    const float* xc[2];
    const float* proj[2];
    const float* xz[2];
    const float* Alog[2];
    const float* Dsk[2];
    float*       yg[2];
};

// ---------------- generic NT SGEMM with register prefetch ----------------
// C[M,N] = A[M,K] * W[N,K]^T. Tile 128 x TN, BK=16, 256 threads.
// TN=128 -> 8x8 microtile; TN=64 -> 8x4.
// EPI: 0=plain store, 1=softplus(v+bias), 2=split-K partial (blockIdx.x = k-slice)
// All of M, N, K are exact multiples of the tiles -> no bounds checks.
template <int TN, int EPI>
__global__ __launch_bounds__(256, 2)
void sgemm_nt(GemmP p, int M, int N, int K, int lda, int ldb, int ldc) {
    const int dir = blockIdx.z;
    const float* __restrict__ A = p.A[dir];
    const float* __restrict__ W = p.W[dir];
    float*       __restrict__ C = p.C[dir];
    const float* bias = p.bias[dir];

    const int cm = blockIdx.y * 128;
    int cn;
    if (EPI == 2) {
        // split-K: blockIdx.x selects the K slice (length = K arg)
        cn = 0;
        A += (size_t)blockIdx.x * K;         // advance K columns of A
        W += (size_t)blockIdx.x * K;         // and of W
        C += (size_t)blockIdx.x * (size_t)M * ldc;  // partial buffer slice
    } else {
        cn = blockIdx.x * TN;
    }

    __shared__ float As[16][128];
    __shared__ float Bs[16][TN];

    constexpr int WN = TN / 16;  // cols per thread
    float acc[8][WN];
#pragma unroll
    for (int i = 0; i < 8; i++)
#pragma unroll
        for (int j = 0; j < WN; j++) acc[i][j] = 0.f;

    const int t  = threadIdx.x;
    const int tr = t >> 4;
    const int tc = t & 15;

    // loader index precompute
    const int ar0 = (t * 2)     >> 2, ak0 = ((t * 2)     & 3) * 4;
    const int ar1 = (t * 2 + 1) >> 2, ak1 = ((t * 2 + 1) & 3) * 4;
    // B loader: TN==128 mirrors A; TN==64 one float4 per thread
    const int br0 = (TN == 128) ? ar0 : (t >> 2);
    const int bk0 = (TN == 128) ? ak0 : ((t & 3) * 4);

    const float* Ap0 = A + (size_t)(cm + ar0) * lda + ak0;
    const float* Ap1 = A + (size_t)(cm + ar1) * lda + ak1;
    const float* Bp0 = W + (size_t)(cn + br0) * ldb + bk0;
    const float* Bp1 = (TN == 128) ? (W + (size_t)(cn + ar1) * ldb + ak1) : nullptr;

    // prologue: stage k0 = 0
    float4 sa0 = *(const float4*)Ap0;
    float4 sa1 = *(const float4*)Ap1;
    float4 sb0 = *(const float4*)Bp0;
    float4 sb1 = (TN == 128) ? *(const float4*)Bp1 : make_float4(0, 0, 0, 0);

    for (int k0 = 0; k0 < K; k0 += 16) {
        // stage -> smem
        As[ak0 + 0][ar0] = sa0.x; As[ak0 + 1][ar0] = sa0.y;
        As[ak0 + 2][ar0] = sa0.z; As[ak0 + 3][ar0] = sa0.w;
        As[ak1 + 0][ar1] = sa1.x; As[ak1 + 1][ar1] = sa1.y;
        As[ak1 + 2][ar1] = sa1.z; As[ak1 + 3][ar1] = sa1.w;
        Bs[bk0 + 0][br0] = sb0.x; Bs[bk0 + 1][br0] = sb0.y;
        Bs[bk0 + 2][br0] = sb0.z; Bs[bk0 + 3][br0] = sb0.w;
        if (TN == 128) {
            Bs[ak1 + 0][ar1] = sb1.x; Bs[ak1 + 1][ar1] = sb1.y;
            Bs[ak1 + 2][ar1] = sb1.z; Bs[ak1 + 3][ar1] = sb1.w;
        }
        __syncthreads();

        // prefetch next k-block while computing this one
        if (k0 + 16 < K) {
            sa0 = *(const float4*)(Ap0 + k0 + 16);
            sa1 = *(const float4*)(Ap1 + k0 + 16);
            sb0 = *(const float4*)(Bp0 + k0 + 16);
            if (TN == 128) sb1 = *(const float4*)(Bp1 + k0 + 16);
        }

#pragma unroll
        for (int k = 0; k < 16; k++) {
            float a[8], bq[WN];
            *(float4*)&a[0] = *(const float4*)&As[k][tr * 8];
            *(float4*)&a[4] = *(const float4*)&As[k][tr * 8 + 4];
            *(float4*)&bq[0] = *(const float4*)&Bs[k][tc * WN];
            if (TN == 128)
                *(float4*)&bq[4] = *(const float4*)&Bs[k][tc * WN + 4];
#pragma unroll
            for (int i = 0; i < 8; i++)
#pragma unroll
                for (int j = 0; j < WN; j++)
                    acc[i][j] = fmaf(a[i], bq[j], acc[i][j]);
        }
        __syncthreads();
    }

#pragma unroll
    for (int i = 0; i < 8; i++) {
        int row = cm + tr * 8 + i;
        float* Crow = C + (size_t)row * ldc + cn + tc * WN;
        if (EPI == 1) {
#pragma unroll
            for (int j = 0; j < WN; j++)
                Crow[j] = softplusf(acc[i][j] + bias[cn + tc * WN + j]);
        } else {
            float4 v0 = make_float4(acc[i][0], acc[i][1], acc[i][2], acc[i][3]);
            *(float4*)(Crow) = v0;
            if (TN == 128) {
                float4 v1 = make_float4(acc[i][4], acc[i][5], acc[i][6], acc[i][7]);
                *(float4*)(Crow + 4) = v1;
            }
        }
    }
}

// ---------------- split-K reduction for proj ----------------
__global__ void reduce_proj_kernel(const float* __restrict__ part,
                                   float* __restrict__ proj) {
    // part layout: [dir][slice][Mrows*64], proj: [dir][Mrows*64]
    int i = blockIdx.x * blockDim.x + threadIdx.x;
    const int per = Mrows * 64;
    if (i >= 2 * per) return;
    int dirn = i / per;
    int off  = i - dirn * per;
    const float* b = part + (size_t)dirn * NSLICE * per + off;
    float s = 0.f;
#pragma unroll
    for (int sidx = 0; sidx < NSLICE; sidx++)
        s += b[(size_t)sidx * per];
    proj[(size_t)dirn * per + off] = s;
}

// ---------------- causal depthwise conv(4) + bias + silu (dir1 reads flipped) ---
__global__ void conv_silu_kernel(ConvP p) {
    const int dir = blockIdx.y;
    const float* __restrict__ xz = p.xz[dir];
    float*       __restrict__ xc = p.xc[dir];
    const float* __restrict__ cw = p.cw[dir];
    const float* __restrict__ cb = p.cb[dir];

    int i = blockIdx.x * blockDim.x + threadIdx.x;
    if (i >= Mrows * DI) return;
    int d  = i & (DI - 1);
    int bl = i >> 10;
    int l  = bl & (Ll - 1);
    int b  = bl >> 11;

    float w0 = cw[d * 4 + 0], w1 = cw[d * 4 + 1], w2 = cw[d * 4 + 2], w3 = cw[d * 4 + 3];
    float s = cb[d];
    // logical sequence index j maps to physical row: dir0 -> j, dir1 -> Ll-1-j
#pragma unroll
    for (int k = 0; k < 4; k++) {
        int j = l - 3 + k;
        if (j >= 0) {
            int pr = (dir == 0) ? j : (Ll - 1 - j);
            float wv = (k == 0) ? w0 : (k == 1) ? w1 : (k == 2) ? w2 : w3;
            s = fmaf(xz[((size_t)b * Ll + pr) * (2 * DI) + d], wv, s);
        }
    }
    xc[i] = siluf(s);
}

// ---------------- selective scan, software-pipelined ----------------
__global__ void scan_kernel(ScanP p) {
    const int dir = blockIdx.y;
    const float* __restrict__ dt   = p.dt[dir];
    const float* __restrict__ xc   = p.xc[dir];
    const float* __restrict__ proj = p.proj[dir];
    const float* __restrict__ xz   = p.xz[dir];
    const float* __restrict__ Alog = p.Alog[dir];
    const float* __restrict__ Dsk  = p.Dsk[dir];
    float*       __restrict__ yg   = p.yg[dir];

    int tid = blockIdx.x * blockDim.x + threadIdx.x;
    int grp = tid >> 4;
    int n   = tid & 15;
    int b = grp >> 10;
    int d = grp & (DI - 1);

    const float Ad = -__expf(Alog[d * DS + n]);
    const float Dv = Dsk[d];
    float h = 0.f;

    const float* pdt = dt   + ((size_t)b * Ll) * DI + d;
    const float* pxc = xc   + ((size_t)b * Ll) * DI + d;
    const float* pBC = proj + ((size_t)b * Ll) * 64;
    // z lives at +DI inside xz rows; dir1 reads physically flipped rows
    const ptrdiff_t zs = (dir == 0) ? (ptrdiff_t)(2 * DI) : -(ptrdiff_t)(2 * DI);
    const float* pz = (dir == 0)
        ? xz + ((size_t)b * Ll) * (2 * DI) + DI + d
        : xz + ((size_t)b * Ll + (Ll - 1)) * (2 * DI) + DI + d;
    float* pyg = yg + ((size_t)b * Ll) * DI + d;

    // depth-1 prefetch pipeline
    float dtv = pdt[0];
    float u   = pxc[0];
    float Bv  = pBC[32 + n];
    float Cv  = pBC[48 + n];
    float zv  = pz[0];

#pragma unroll 2
    for (int l = 0; l < Ll; l++) {
        float ndt = 0.f, nu = 0.f, nB = 0.f, nC = 0.f, nz = 0.f;
        if (l + 1 < Ll) {
            ndt = pdt[(size_t)(l + 1) * DI];
            nu  = pxc[(size_t)(l + 1) * DI];
            nB  = pBC[(size_t)(l + 1) * 64 + 32 + n];
            nC  = pBC[(size_t)(l + 1) * 64 + 48 + n];
            nz  = pz[(ptrdiff_t)(l + 1) * zs];
        }
        float dA = __expf(dtv * Ad);
        h = fmaf(dA, h, dtv * Bv * u);
        float y = h * Cv;
        y += __shfl_xor_sync(0xffffffffu, y, 8);
        y += __shfl_xor_sync(0xffffffffu, y, 4);
        y += __shfl_xor_sync(0xffffffffu, y, 2);
        y += __shfl_xor_sync(0xffffffffu, y, 1);
        if (n == 0)
            pyg[(size_t)l * DI] = (y + u * Dv) * siluf(zv);
        dtv = ndt; u = nu; Bv = nB; Cv = nC; zv = nz;
    }
}

// ---------------- combine fw + flipped bw, LayerNorm, silu + residual ----------
__global__ void combine_kernel(const float* __restrict__ f,
                               const float* __restrict__ bw,
                               const float* __restrict__ x,
                               const float* __restrict__ g,
                               const float* __restrict__ beta,
                               float* __restrict__ out) {
    int row = blockIdx.x;              // b*L + l
    int b = row >> 11;
    int l = row & (Ll - 1);
    const float* fr = f  + (size_t)row * DM;
    const float* br = bw + ((size_t)b * Ll + (Ll - 1 - l)) * DM;

    int c0 = threadIdx.x;
    int c1 = threadIdx.x + 256;
    float v0 = 0.5f * (fr[c0] + br[c0]);
    float v1 = 0.5f * (fr[c1] + br[c1]);

    float s1 = v0 + v1;
    float s2 = v0 * v0 + v1 * v1;
#pragma unroll
    for (int o = 16; o; o >>= 1) {
        s1 += __shfl_xor_sync(0xffffffffu, s1, o);
        s2 += __shfl_xor_sync(0xffffffffu, s2, o);
    }
    __shared__ float sh1[8], sh2[8];
    __shared__ float s_mu, s_rstd;
    int w = threadIdx.x >> 5, ln = threadIdx.x & 31;
    if (ln == 0) { sh1[w] = s1; sh2[w] = s2; }
    __syncthreads();
    if (threadIdx.x == 0) {
        float a = 0.f, q = 0.f;
#pragma unroll
        for (int i = 0; i < 8; i++) { a += sh1[i]; q += sh2[i]; }
        float mu  = a * (1.f / DM);
        float var = q * (1.f / DM) - mu * mu;
        s_mu   = mu;
        s_rstd = rsqrtf(var + 1e-5f);
    }
    __syncthreads();
    float mu = s_mu, rstd = s_rstd;
    const float* xr = x + (size_t)row * DM;
    float o0 = (v0 - mu) * rstd * g[c0] + beta[c0];
    float o1 = (v1 - mu) * rstd * g[c1] + beta[c1];
    out[(size_t)row * DM + c0] = siluf(o0) + xr[c0];
    out[(size_t)row * DM + c1] = siluf(o1) + xr[c1];
}

// ---------------- launch ----------------
extern "C" void kernel_launch(void* const* d_in, const int* in_sizes, int n_in,
                              void* d_out, int out_size) {
    const float* x = (const float*)d_in[0];
    const float* fW_in  = (const float*)d_in[1];
    const float* fcw    = (const float*)d_in[2];
    const float* fcb    = (const float*)d_in[3];
    const float* fWxp   = (const float*)d_in[4];
    const float* fWdt   = (const float*)d_in[5];
    const float* fbdt   = (const float*)d_in[6];
    const float* fAlog  = (const float*)d_in[7];
    const float* fDsk   = (const float*)d_in[8];
    const float* fWout  = (const float*)d_in[9];
    const float* bW_in  = (const float*)d_in[10];
    const float* bcw    = (const float*)d_in[11];
    const float* bcb    = (const float*)d_in[12];
    const float* bWxp   = (const float*)d_in[13];
    const float* bWdt   = (const float*)d_in[14];
    const float* bbdt   = (const float*)d_in[15];
    const float* bAlog  = (const float*)d_in[16];
    const float* bDsk   = (const float*)d_in[17];
    const float* bWout  = (const float*)d_in[18];
    const float* ln_g   = (const float*)d_in[19];
    const float* ln_b   = (const float*)d_in[20];
    float* out = (float*)d_out;

    float *xz, *xc, *proj, *pp, *dtb, *ygb, *od;
    cudaGetSymbolAddress((void**)&xz,   g_xz);
    cudaGetSymbolAddress((void**)&xc,   g_xc);
    cudaGetSymbolAddress((void**)&proj, g_proj);
    cudaGetSymbolAddress((void**)&pp,   g_pp);
    cudaGetSymbolAddress((void**)&dtb,  g_dt);
    cudaGetSymbolAddress((void**)&ygb,  g_yg);
    cudaGetSymbolAddress((void**)&od,   g_od);

    const size_t SXZ = (size_t)Mrows * 2 * DI;
    const size_t SXC = (size_t)Mrows * DI;
    const size_t SPJ = (size_t)Mrows * 64;
    const size_t SOD = (size_t)Mrows * DM;

    float* xz0 = xz;   float* xz1 = xz + SXZ;
    float* xc0 = xc;   float* xc1 = xc + SXC;
    float* pj0 = proj; float* pj1 = proj + SPJ;
    float* pp0 = pp;   float* pp1 = pp + (size_t)NSLICE * SPJ;
    float* dt0 = dtb;  float* dt1 = dtb + SXC;
    float* yg0 = ygb;  float* yg1 = ygb + SXC;
    float* od0 = od;   float* od1 = od + SOD;

    // 1. GEMM1: xz' = x * W_in^T (both dirs share un-flipped A; conv flips dir1)
    {
        GemmP p;
        p.A[0] = x;     p.A[1] = x;
        p.W[0] = fW_in; p.W[1] = bW_in;
        p.C[0] = xz0;   p.C[1] = xz1;
        p.bias[0] = nullptr; p.bias[1] = nullptr;
        dim3 grid(2 * DI / 128, Mrows / 128, 2);
        sgemm_nt<128, 0><<<grid, 256>>>(p, Mrows, 2 * DI, DM, DM, DM, 2 * DI);
    }

    // 2. conv + silu (dir1 reads flipped rows; xc1 comes out in bw order)
    {
        ConvP p;
        p.xz[0] = xz0; p.xz[1] = xz1;
        p.xc[0] = xc0; p.xc[1] = xc1;
        p.cw[0] = fcw; p.cw[1] = bcw;
        p.cb[0] = fcb; p.cb[1] = bcb;
        dim3 grid((Mrows * DI + 255) / 256, 2);
        conv_silu_kernel<<<grid, 256>>>(p);
    }

    // 3. GEMM2 split-K: partial = xc * Wxp^T over K slices of 128
    {
        GemmP p;
        p.A[0] = xc0;  p.A[1] = xc1;
        p.W[0] = fWxp; p.W[1] = bWxp;
        p.C[0] = pp0;  p.C[1] = pp1;
        p.bias[0] = nullptr; p.bias[1] = nullptr;
        dim3 grid(NSLICE, Mrows / 128, 2);
        sgemm_nt<64, 2><<<grid, 256>>>(p, Mrows, 64, DI / NSLICE, DI, DI, 64);
    }

    // 4. reduce split-K partials
    reduce_proj_kernel<<<(2 * Mrows * 64 + 255) / 256, 256>>>(pp, proj);

    // 5. GEMM3: dt = softplus(dtpart * Wdt^T + b_dt)
    {
        GemmP p;
        p.A[0] = pj0;  p.A[1] = pj1;
        p.W[0] = fWdt; p.W[1] = bWdt;
        p.C[0] = dt0;  p.C[1] = dt1;
        p.bias[0] = fbdt; p.bias[1] = bbdt;
        dim3 grid(DI / 128, Mrows / 128, 2);
        sgemm_nt<128, 1><<<grid, 256>>>(p, Mrows, DI, DR, 64, DR, DI);
    }

    // 6. scan (+ D skip + z gate; dir1 reads z from flipped rows)
    {
        ScanP p;
        p.dt[0] = dt0;   p.dt[1] = dt1;
        p.xc[0] = xc0;   p.xc[1] = xc1;
        p.proj[0] = pj0; p.proj[1] = pj1;
        p.xz[0] = xz0;   p.xz[1] = xz1;
        p.Alog[0] = fAlog; p.Alog[1] = bAlog;
        p.Dsk[0] = fDsk;   p.Dsk[1] = bDsk;
        p.yg[0] = yg0;   p.yg[1] = yg1;
        dim3 grid((Bb * DI * DS) / 256, 2);
        scan_kernel<<<grid, 256>>>(p);
    }

    // 7. GEMM4: od = yg * Wout^T
    {
        GemmP p;
        p.A[0] = yg0;   p.A[1] = yg1;
        p.W[0] = fWout; p.W[1] = bWout;
        p.C[0] = od0;   p.C[1] = od1;
        p.bias[0] = nullptr; p.bias[1] = nullptr;
        dim3 grid(DM / 128, Mrows / 128, 2);
        sgemm_nt<128, 0><<<grid, 256>>>(p, Mrows, DM, DI, DI, DI, DM);
    }

    // 8. combine + LN + silu + residual (flips od1 back)
    combine_kernel<<<Mrows, 256>>>(od0, od1, x, ln_g, ln_b, out);
}

// round 3
// speedup vs baseline: 2.2139x; 1.3141x over previous
#include <cuda_runtime.h>
#include <cuda_bf16.h>
#include <math.h>

// ---------------- problem constants ----------------
#define Bb 2
#define Ll 2048
#define DM 512
#define DI 1024
#define DS 16
#define DR 32
#define Mrows (Bb*Ll)          // 4096
#define NSLICE 8               // split-K slices for GEMM2

// ---------------- scratch (device globals; allocation-free) ----------------
__device__ float g_xz  [2][(size_t)Mrows*2*DI];
__device__ float g_xc  [2][(size_t)Mrows*DI];
__device__ float g_proj[2][(size_t)Mrows*64];
__device__ float g_pp  [2][NSLICE][(size_t)Mrows*64];
__device__ float g_dt  [2][(size_t)Mrows*DI];
__device__ float g_yg  [2][(size_t)Mrows*DI];
__device__ float g_od  [2][(size_t)Mrows*DM];

// ---------------- helpers ----------------
__device__ __forceinline__ float softplusf(float x) {
    return fmaxf(x, 0.f) + log1pf(__expf(-fabsf(x)));
}
__device__ __forceinline__ float siluf(float x) {
    return x / (1.f + __expf(-x));
}
__device__ __forceinline__ unsigned f2tf(float f) {
    unsigned u;
    asm("cvt.rna.tf32.f32 %0, %1;" : "=r"(u) : "f"(f));
    return u;
}
__device__ __forceinline__ void mma_tf32(float c[4], const unsigned a[4], const unsigned b[2]) {
    asm volatile(
        "mma.sync.aligned.m16n8k8.row.col.f32.tf32.tf32.f32 "
        "{%0,%1,%2,%3}, {%4,%5,%6,%7}, {%8,%9}, {%0,%1,%2,%3};\n"
        : "+f"(c[0]), "+f"(c[1]), "+f"(c[2]), "+f"(c[3])
        : "r"(a[0]), "r"(a[1]), "r"(a[2]), "r"(a[3]), "r"(b[0]), "r"(b[1]));
}

// ---------------- param structs (2 directions) ----------------
struct GemmP {
    const float* A[2];
    const float* W[2];
    float*       C[2];
    const float* bias[2];
};
struct ConvP {
    const float* xz[2];
    float*       xc[2];
    const float* cw[2];
    const float* cb[2];
};
struct ScanP {
    const float* dt[2];
    const float* xc[2];
    const float* proj[2];
    const float* xz[2];
    const float* Alog[2];
    const float* Dsk[2];
    float*       yg[2];
};

// ================= tf32 tensor-core NT GEMM =================
// C[M,N] = A[M,K] * W[N,K]^T, fp32 in/out, tf32 mma accumulate fp32.
// Block tile 128x128, BK=16, 256 threads = 8 warps (2x4), warp tile 64x32.
// M % 128 == 0, N % 128 == 0, K % 16 == 0 (no bounds checks).
// EPI: 0 = plain store, 1 = softplus(v + bias[col]).
template <int EPI>
__global__ __launch_bounds__(256, 2)
void tgemm_nt(GemmP p, int M, int N, int K, int lda, int ldb, int ldc) {
    const int dir = blockIdx.z;
    const float* __restrict__ A = p.A[dir];
    const float* __restrict__ W = p.W[dir];
    float*       __restrict__ C = p.C[dir];
    const float* bias = p.bias[dir];

    const int cm = blockIdx.y * 128;
    const int cn = blockIdx.x * 128;

    __shared__ unsigned As[128][36];   // [m][k], stride 36 -> conflict-free frags
    __shared__ unsigned Bs[128][36];   // [n][k]

    const int t    = threadIdx.x;
    const int lane = t & 31;
    const int wid  = t >> 5;
    const int wm   = (wid >> 2) * 64;   // warp m offset (0 or 64)
    const int wn   = (wid & 3) * 32;    // warp n offset (0..96)
    const int l4   = lane >> 2;
    const int lm   = lane & 3;

    float acc[4][4][4];
#pragma unroll
    for (int mi = 0; mi < 4; mi++)
#pragma unroll
        for (int ni = 0; ni < 4; ni++)
#pragma unroll
            for (int r = 0; r < 4; r++) acc[mi][ni][r] = 0.f;

    // loaders: thread covers rows arow, arow+64; 4 k-floats at acol
    const int arow = t >> 2;          // 0..63
    const int acol = (t & 3) * 4;     // 0,4,8,12
    const float* Ap = A + (size_t)(cm + arow) * lda + acol;
    const float* Bp = W + (size_t)(cn + arow) * ldb + acol;

    float4 sa0 = *(const float4*)(Ap);
    float4 sa1 = *(const float4*)(Ap + (size_t)64 * lda);
    float4 sb0 = *(const float4*)(Bp);
    float4 sb1 = *(const float4*)(Bp + (size_t)64 * ldb);

    for (int k0 = 0; k0 < K; k0 += 16) {
        // convert + stage to smem
        {
            uint4 u;
            u.x = f2tf(sa0.x); u.y = f2tf(sa0.y); u.z = f2tf(sa0.z); u.w = f2tf(sa0.w);
            *(uint4*)&As[arow][acol] = u;
            u.x = f2tf(sa1.x); u.y = f2tf(sa1.y); u.z = f2tf(sa1.z); u.w = f2tf(sa1.w);
            *(uint4*)&As[arow + 64][acol] = u;
            u.x = f2tf(sb0.x); u.y = f2tf(sb0.y); u.z = f2tf(sb0.z); u.w = f2tf(sb0.w);
            *(uint4*)&Bs[arow][acol] = u;
            u.x = f2tf(sb1.x); u.y = f2tf(sb1.y); u.z = f2tf(sb1.z); u.w = f2tf(sb1.w);
            *(uint4*)&Bs[arow + 64][acol] = u;
        }
        __syncthreads();

        // prefetch next k-block
        if (k0 + 16 < K) {
            sa0 = *(const float4*)(Ap + k0 + 16);
            sa1 = *(const float4*)(Ap + (size_t)64 * lda + k0 + 16);
            sb0 = *(const float4*)(Bp + k0 + 16);
            sb1 = *(const float4*)(Bp + (size_t)64 * ldb + k0 + 16);
        }

#pragma unroll
        for (int ks = 0; ks < 2; ks++) {
            const int kk = ks * 8;
            unsigned af[4][4], bf[4][2];
#pragma unroll
            for (int mi = 0; mi < 4; mi++) {
                int mr = wm + mi * 16 + l4;
                af[mi][0] = As[mr][kk + lm];
                af[mi][1] = As[mr + 8][kk + lm];
                af[mi][2] = As[mr][kk + 4 + lm];
                af[mi][3] = As[mr + 8][kk + 4 + lm];
            }
#pragma unroll
            for (int ni = 0; ni < 4; ni++) {
                int nr = wn + ni * 8 + l4;
                bf[ni][0] = Bs[nr][kk + lm];
                bf[ni][1] = Bs[nr][kk + 4 + lm];
            }
#pragma unroll
            for (int mi = 0; mi < 4; mi++)
#pragma unroll
                for (int ni = 0; ni < 4; ni++)
                    mma_tf32(acc[mi][ni], af[mi], bf[ni]);
        }
        __syncthreads();
    }

    // epilogue: c0,c1 -> (row, col..col+1); c2,c3 -> (row+8, col..col+1)
#pragma unroll
    for (int mi = 0; mi < 4; mi++) {
#pragma unroll
        for (int ni = 0; ni < 4; ni++) {
            int row = cm + wm + mi * 16 + l4;
            int col = cn + wn + ni * 8 + 2 * lm;
            float v0 = acc[mi][ni][0], v1 = acc[mi][ni][1];
            float v2 = acc[mi][ni][2], v3 = acc[mi][ni][3];
            if (EPI == 1) {
                float b0 = bias[col], b1 = bias[col + 1];
                v0 = softplusf(v0 + b0); v1 = softplusf(v1 + b1);
                v2 = softplusf(v2 + b0); v3 = softplusf(v3 + b1);
            }
            *(float2*)(C + (size_t)row * ldc + col)       = make_float2(v0, v1);
            *(float2*)(C + (size_t)(row + 8) * ldc + col) = make_float2(v2, v3);
        }
    }
}

// ================= fp32 SGEMM (kept for GEMM2 split-K, TN=64) =================
template <int TN, int EPI>
__global__ __launch_bounds__(256, 2)
void sgemm_nt(GemmP p, int M, int N, int K, int lda, int ldb, int ldc) {
    const int dir = blockIdx.z;
    const float* __restrict__ A = p.A[dir];
    const float* __restrict__ W = p.W[dir];
    float*       __restrict__ C = p.C[dir];

    const int cm = blockIdx.y * 128;
    int cn;
    if (EPI == 2) {
        cn = 0;
        A += (size_t)blockIdx.x * K;
        W += (size_t)blockIdx.x * K;
        C += (size_t)blockIdx.x * (size_t)M * ldc;
    } else {
        cn = blockIdx.x * TN;
    }

    __shared__ float As[16][128];
    __shared__ float Bs[16][TN];

    constexpr int WN = TN / 16;
    float acc[8][WN];
#pragma unroll
    for (int i = 0; i < 8; i++)
#pragma unroll
        for (int j = 0; j < WN; j++) acc[i][j] = 0.f;

    const int t  = threadIdx.x;
    const int tr = t >> 4;
    const int tc = t & 15;

    const int ar0 = (t * 2)     >> 2, ak0 = ((t * 2)     & 3) * 4;
    const int ar1 = (t * 2 + 1) >> 2, ak1 = ((t * 2 + 1) & 3) * 4;
    const int br0 = (TN == 128) ? ar0 : (t >> 2);
    const int bk0 = (TN == 128) ? ak0 : ((t & 3) * 4);

    const float* Ap0 = A + (size_t)(cm + ar0) * lda + ak0;
    const float* Ap1 = A + (size_t)(cm + ar1) * lda + ak1;
    const float* Bp0 = W + (size_t)(cn + br0) * ldb + bk0;
    const float* Bp1 = (TN == 128) ? (W + (size_t)(cn + ar1) * ldb + ak1) : nullptr;

    float4 sa0 = *(const float4*)Ap0;
    float4 sa1 = *(const float4*)Ap1;
    float4 sb0 = *(const float4*)Bp0;
    float4 sb1 = (TN == 128) ? *(const float4*)Bp1 : make_float4(0, 0, 0, 0);

    for (int k0 = 0; k0 < K; k0 += 16) {
        As[ak0 + 0][ar0] = sa0.x; As[ak0 + 1][ar0] = sa0.y;
        As[ak0 + 2][ar0] = sa0.z; As[ak0 + 3][ar0] = sa0.w;
        As[ak1 + 0][ar1] = sa1.x; As[ak1 + 1][ar1] = sa1.y;
        As[ak1 + 2][ar1] = sa1.z; As[ak1 + 3][ar1] = sa1.w;
        Bs[bk0 + 0][br0] = sb0.x; Bs[bk0 + 1][br0] = sb0.y;
        Bs[bk0 + 2][br0] = sb0.z; Bs[bk0 + 3][br0] = sb0.w;
        if (TN == 128) {
            Bs[ak1 + 0][ar1] = sb1.x; Bs[ak1 + 1][ar1] = sb1.y;
            Bs[ak1 + 2][ar1] = sb1.z; Bs[ak1 + 3][ar1] = sb1.w;
        }
        __syncthreads();

        if (k0 + 16 < K) {
            sa0 = *(const float4*)(Ap0 + k0 + 16);
            sa1 = *(const float4*)(Ap1 + k0 + 16);
            sb0 = *(const float4*)(Bp0 + k0 + 16);
            if (TN == 128) sb1 = *(const float4*)(Bp1 + k0 + 16);
        }

#pragma unroll
        for (int k = 0; k < 16; k++) {
            float a[8], bq[WN];
            *(float4*)&a[0] = *(const float4*)&As[k][tr * 8];
            *(float4*)&a[4] = *(const float4*)&As[k][tr * 8 + 4];
            *(float4*)&bq[0] = *(const float4*)&Bs[k][tc * WN];
            if (TN == 128)
                *(float4*)&bq[4] = *(const float4*)&Bs[k][tc * WN + 4];
#pragma unroll
            for (int i = 0; i < 8; i++)
#pragma unroll
                for (int j = 0; j < WN; j++)
                    acc[i][j] = fmaf(a[i], bq[j], acc[i][j]);
        }
        __syncthreads();
    }

#pragma unroll
    for (int i = 0; i < 8; i++) {
        int row = cm + tr * 8 + i;
        float* Crow = C + (size_t)row * ldc + cn + tc * WN;
        float4 v0 = make_float4(acc[i][0], acc[i][1], acc[i][2], acc[i][3]);
        *(float4*)(Crow) = v0;
        if (TN == 128) {
            float4 v1 = make_float4(acc[i][4], acc[i][5], acc[i][6], acc[i][7]);
            *(float4*)(Crow + 4) = v1;
        }
    }
}

// ---------------- split-K reduction for proj ----------------
__global__ void reduce_proj_kernel(const float* __restrict__ part,
                                   float* __restrict__ proj) {
    int i = blockIdx.x * blockDim.x + threadIdx.x;
    const int per = Mrows * 64;
    if (i >= 2 * per) return;
    int dirn = i / per;
    int off  = i - dirn * per;
    const float* b = part + (size_t)dirn * NSLICE * per + off;
    float s = 0.f;
#pragma unroll
    for (int sidx = 0; sidx < NSLICE; sidx++)
        s += b[(size_t)sidx * per];
    proj[(size_t)dirn * per + off] = s;
}

// ---------------- causal depthwise conv(4) + bias + silu (dir1 reads flipped) ---
__global__ void conv_silu_kernel(ConvP p) {
    const int dir = blockIdx.y;
    const float* __restrict__ xz = p.xz[dir];
    float*       __restrict__ xc = p.xc[dir];
    const float* __restrict__ cw = p.cw[dir];
    const float* __restrict__ cb = p.cb[dir];

    int i = blockIdx.x * blockDim.x + threadIdx.x;
    if (i >= Mrows * DI) return;
    int d  = i & (DI - 1);
    int bl = i >> 10;
    int l  = bl & (Ll - 1);
    int b  = bl >> 11;

    float w0 = cw[d * 4 + 0], w1 = cw[d * 4 + 1], w2 = cw[d * 4 + 2], w3 = cw[d * 4 + 3];
    float s = cb[d];
#pragma unroll
    for (int k = 0; k < 4; k++) {
        int j = l - 3 + k;
        if (j >= 0) {
            int pr = (dir == 0) ? j : (Ll - 1 - j);
            float wv = (k == 0) ? w0 : (k == 1) ? w1 : (k == 2) ? w2 : w3;
            s = fmaf(xz[((size_t)b * Ll + pr) * (2 * DI) + d], wv, s);
        }
    }
    xc[i] = siluf(s);
}

// ---------------- selective scan, software-pipelined ----------------
__global__ void scan_kernel(ScanP p) {
    const int dir = blockIdx.y;
    const float* __restrict__ dt   = p.dt[dir];
    const float* __restrict__ xc   = p.xc[dir];
    const float* __restrict__ proj = p.proj[dir];
    const float* __restrict__ xz   = p.xz[dir];
    const float* __restrict__ Alog = p.Alog[dir];
    const float* __restrict__ Dsk  = p.Dsk[dir];
    float*       __restrict__ yg   = p.yg[dir];

    int tid = blockIdx.x * blockDim.x + threadIdx.x;
    int grp = tid >> 4;
    int n   = tid & 15;
    int b = grp >> 10;
    int d = grp & (DI - 1);

    const float Ad = -__expf(Alog[d * DS + n]);
    const float Dv = Dsk[d];
    float h = 0.f;

    const float* pdt = dt   + ((size_t)b * Ll) * DI + d;
    const float* pxc = xc   + ((size_t)b * Ll) * DI + d;
    const float* pBC = proj + ((size_t)b * Ll) * 64;
    const ptrdiff_t zs = (dir == 0) ? (ptrdiff_t)(2 * DI) : -(ptrdiff_t)(2 * DI);
    const float* pz = (dir == 0)
        ? xz + ((size_t)b * Ll) * (2 * DI) + DI + d
        : xz + ((size_t)b * Ll + (Ll - 1)) * (2 * DI) + DI + d;
    float* pyg = yg + ((size_t)b * Ll) * DI + d;

    float dtv = pdt[0];
    float u   = pxc[0];
    float Bv  = pBC[32 + n];
    float Cv  = pBC[48 + n];
    float zv  = pz[0];

#pragma unroll 2
    for (int l = 0; l < Ll; l++) {
        float ndt = 0.f, nu = 0.f, nB = 0.f, nC = 0.f, nz = 0.f;
        if (l + 1 < Ll) {
            ndt = pdt[(size_t)(l + 1) * DI];
            nu  = pxc[(size_t)(l + 1) * DI];
            nB  = pBC[(size_t)(l + 1) * 64 + 32 + n];
            nC  = pBC[(size_t)(l + 1) * 64 + 48 + n];
            nz  = pz[(ptrdiff_t)(l + 1) * zs];
        }
        float dA = __expf(dtv * Ad);
        h = fmaf(dA, h, dtv * Bv * u);
        float y = h * Cv;
        y += __shfl_xor_sync(0xffffffffu, y, 8);
        y += __shfl_xor_sync(0xffffffffu, y, 4);
        y += __shfl_xor_sync(0xffffffffu, y, 2);
        y += __shfl_xor_sync(0xffffffffu, y, 1);
        if (n == 0)
            pyg[(size_t)l * DI] = (y + u * Dv) * siluf(zv);
        dtv = ndt; u = nu; Bv = nB; Cv = nC; zv = nz;
    }
}

// ---------------- combine fw + flipped bw, LayerNorm, silu + residual ----------
__global__ void combine_kernel(const float* __restrict__ f,
                               const float* __restrict__ bw,
                               const float* __restrict__ x,
                               const float* __restrict__ g,
                               const float* __restrict__ beta,
                               float* __restrict__ out) {
    int row = blockIdx.x;
    int b = row >> 11;
    int l = row & (Ll - 1);
    const float* fr = f  + (size_t)row * DM;
    const float* br = bw + ((size_t)b * Ll + (Ll - 1 - l)) * DM;

    int c0 = threadIdx.x;
    int c1 = threadIdx.x + 256;
    float v0 = 0.5f * (fr[c0] + br[c0]);
    float v1 = 0.5f * (fr[c1] + br[c1]);

    float s1 = v0 + v1;
    float s2 = v0 * v0 + v1 * v1;
#pragma unroll
    for (int o = 16; o; o >>= 1) {
        s1 += __shfl_xor_sync(0xffffffffu, s1, o);
        s2 += __shfl_xor_sync(0xffffffffu, s2, o);
    }
    __shared__ float sh1[8], sh2[8];
    __shared__ float s_mu, s_rstd;
    int w = threadIdx.x >> 5, ln = threadIdx.x & 31;
    if (ln == 0) { sh1[w] = s1; sh2[w] = s2; }
    __syncthreads();
    if (threadIdx.x == 0) {
        float a = 0.f, q = 0.f;
#pragma unroll
        for (int i = 0; i < 8; i++) { a += sh1[i]; q += sh2[i]; }
        float mu  = a * (1.f / DM);
        float var = q * (1.f / DM) - mu * mu;
        s_mu   = mu;
        s_rstd = rsqrtf(var + 1e-5f);
    }
    __syncthreads();
    float mu = s_mu, rstd = s_rstd;
    const float* xr = x + (size_t)row * DM;
    float o0 = (v0 - mu) * rstd * g[c0] + beta[c0];
    float o1 = (v1 - mu) * rstd * g[c1] + beta[c1];
    out[(size_t)row * DM + c0] = siluf(o0) + xr[c0];
    out[(size_t)row * DM + c1] = siluf(o1) + xr[c1];
}

// ---------------- launch ----------------
extern "C" void kernel_launch(void* const* d_in, const int* in_sizes, int n_in,
                              void* d_out, int out_size) {
    const float* x = (const float*)d_in[0];
    const float* fW_in  = (const float*)d_in[1];
    const float* fcw    = (const float*)d_in[2];
    const float* fcb    = (const float*)d_in[3];
    const float* fWxp   = (const float*)d_in[4];
    const float* fWdt   = (const float*)d_in[5];
    const float* fbdt   = (const float*)d_in[6];
    const float* fAlog  = (const float*)d_in[7];
    const float* fDsk   = (const float*)d_in[8];
    const float* fWout  = (const float*)d_in[9];
    const float* bW_in  = (const float*)d_in[10];
    const float* bcw    = (const float*)d_in[11];
    const float* bcb    = (const float*)d_in[12];
    const float* bWxp   = (const float*)d_in[13];
    const float* bWdt   = (const float*)d_in[14];
    const float* bbdt   = (const float*)d_in[15];
    const float* bAlog  = (const float*)d_in[16];
    const float* bDsk   = (const float*)d_in[17];
    const float* bWout  = (const float*)d_in[18];
    const float* ln_g   = (const float*)d_in[19];
    const float* ln_b   = (const float*)d_in[20];
    float* out = (float*)d_out;

    float *xz, *xc, *proj, *pp, *dtb, *ygb, *od;
    cudaGetSymbolAddress((void**)&xz,   g_xz);
    cudaGetSymbolAddress((void**)&xc,   g_xc);
    cudaGetSymbolAddress((void**)&proj, g_proj);
    cudaGetSymbolAddress((void**)&pp,   g_pp);
    cudaGetSymbolAddress((void**)&dtb,  g_dt);
    cudaGetSymbolAddress((void**)&ygb,  g_yg);
    cudaGetSymbolAddress((void**)&od,   g_od);

    const size_t SXZ = (size_t)Mrows * 2 * DI;
    const size_t SXC = (size_t)Mrows * DI;
    const size_t SPJ = (size_t)Mrows * 64;
    const size_t SOD = (size_t)Mrows * DM;

    float* xz0 = xz;   float* xz1 = xz + SXZ;
    float* xc0 = xc;   float* xc1 = xc + SXC;
    float* pj0 = proj; float* pj1 = proj + SPJ;
    float* pp0 = pp;   float* pp1 = pp + (size_t)NSLICE * SPJ;
    float* dt0 = dtb;  float* dt1 = dtb + SXC;
    float* yg0 = ygb;  float* yg1 = ygb + SXC;
    float* od0 = od;   float* od1 = od + SOD;

    // 1. GEMM1 (tf32): xz' = x * W_in^T (both dirs share un-flipped A)
    {
        GemmP p;
        p.A[0] = x;     p.A[1] = x;
        p.W[0] = fW_in; p.W[1] = bW_in;
        p.C[0] = xz0;   p.C[1] = xz1;
        p.bias[0] = nullptr; p.bias[1] = nullptr;
        dim3 grid(2 * DI / 128, Mrows / 128, 2);
        tgemm_nt<0><<<grid, 256>>>(p, Mrows, 2 * DI, DM, DM, DM, 2 * DI);
    }

    // 2. conv + silu (dir1 reads flipped rows; xc1 comes out in bw order)
    {
        ConvP p;
        p.xz[0] = xz0; p.xz[1] = xz1;
        p.xc[0] = xc0; p.xc[1] = xc1;
        p.cw[0] = fcw; p.cw[1] = bcw;
        p.cb[0] = fcb; p.cb[1] = bcb;
        dim3 grid((Mrows * DI + 255) / 256, 2);
        conv_silu_kernel<<<grid, 256>>>(p);
    }

    // 3. GEMM2 split-K (fp32): partial = xc * Wxp^T over K slices of 128
    {
        GemmP p;
        p.A[0] = xc0;  p.A[1] = xc1;
        p.W[0] = fWxp; p.W[1] = bWxp;
        p.C[0] = pp0;  p.C[1] = pp1;
        p.bias[0] = nullptr; p.bias[1] = nullptr;
        dim3 grid(NSLICE, Mrows / 128, 2);
        sgemm_nt<64, 2><<<grid, 256>>>(p, Mrows, 64, DI / NSLICE, DI, DI, 64);
    }

    // 4. reduce split-K partials
    reduce_proj_kernel<<<(2 * Mrows * 64 + 255) / 256, 256>>>(pp, proj);

    // 5. GEMM3 (tf32): dt = softplus(dtpart * Wdt^T + b_dt)
    {
        GemmP p;
        p.A[0] = pj0;  p.A[1] = pj1;
        p.W[0] = fWdt; p.W[1] = bWdt;
        p.C[0] = dt0;  p.C[1] = dt1;
        p.bias[0] = fbdt; p.bias[1] = bbdt;
        dim3 grid(DI / 128, Mrows / 128, 2);
        tgemm_nt<1><<<grid, 256>>>(p, Mrows, DI, DR, 64, DR, DI);
    }

    // 6. scan (+ D skip + z gate; dir1 reads z from flipped rows)
    {
        ScanP p;
        p.dt[0] = dt0;   p.dt[1] = dt1;
        p.xc[0] = xc0;   p.xc[1] = xc1;
        p.proj[0] = pj0; p.proj[1] = pj1;
        p.xz[0] = xz0;   p.xz[1] = xz1;
        p.Alog[0] = fAlog; p.Alog[1] = bAlog;
        p.Dsk[0] = fDsk;   p.Dsk[1] = bDsk;
        p.yg[0] = yg0;   p.yg[1] = yg1;
        dim3 grid((Bb * DI * DS) / 256, 2);
        scan_kernel<<<grid, 256>>>(p);
    }

    // 7. GEMM4 (tf32): od = yg * Wout^T
    {
        GemmP p;
        p.A[0] = yg0;   p.A[1] = yg1;
        p.W[0] = fWout; p.W[1] = bWout;
        p.C[0] = od0;   p.C[1] = od1;
        p.bias[0] = nullptr; p.bias[1] = nullptr;
        dim3 grid(DM / 128, Mrows / 128, 2);
        tgemm_nt<0><<<grid, 256>>>(p, Mrows, DM, DI, DI, DI, DM);
    }

    // 8. combine + LN + silu + residual (flips od1 back)
    combine_kernel<<<Mrows, 256>>>(od0, od1, x, ln_g, ln_b, out);
}